// round 2
// baseline (speedup 1.0000x reference)
#include <cuda_runtime.h>
#include <cstdint>

// Dense 2D spatial transformer (bilinear warp, zero-padded border) — smem-tiled.
//
// input1: [1,1,4096,4096] f32 image
// input2: [1,2,4096,4096] f32 flow (plane 0 = dH, plane 1 = dW)
// out:    [1,1,4096,4096] f32
//
// Reference semantics (padded coords p in [0,4097], padded image zero at p=0 and 4097):
//   H_up = flow_h + h + 1 ; W_up = flow_w + w + 1
//   hf = clip(floor(H_up),0,4097); hc = clip(hf+1,0,4097); same for w
//   dH = hc - H_up; dW = wc - W_up  (weights from CLIPPED coords)
//   out = v(hf,wf)*dW*dH + v(hc,wf)*dW*(1-dH) + v(hf,wc)*(1-dW)*dH + v(hc,wc)*(1-dW)*(1-dH)
//
// Strategy: 64x64 pixel tile per 256-thread block. Stage an 82x82 padded window
// (halo 8) into shared memory; all 4 bilinear taps become LDS. Flow N(0,1) means
// the global-memory fallback (taps outside halo) is essentially never taken, but
// it preserves exact correctness for arbitrary flows.

#define H_DIM 4096
#define W_DIM 4096
#define HP_MAX 4097       // padded max index
#define TILE 64
#define HALO 8
#define SDIM (TILE + 2 * HALO + 2)   // 82 (need floor and floor+1)
#define SSTR (SDIM + 2)              // 84, padded row stride

__device__ __forceinline__ float fetch_padded(const float* __restrict__ img, int h, int w) {
    bool in = (h >= 1) & (h <= H_DIM) & (w >= 1) & (w <= W_DIM);
    return in ? __ldg(img + (size_t)(h - 1) * W_DIM + (w - 1)) : 0.0f;
}

__device__ __forceinline__ float warp_one(const float* __restrict__ s,
                                          const float* __restrict__ img,
                                          float f_h, float f_w,
                                          int h, int w, int ph0, int pw0) {
    float Hu = f_h + (float)(h + 1);
    float Wu = f_w + (float)(w + 1);

    int hf = __float2int_rd(Hu);   // floor
    int wf = __float2int_rd(Wu);
    int hc = hf + 1;
    int wc = wf + 1;

    hf = min(max(hf, 0), HP_MAX);
    hc = min(max(hc, 0), HP_MAX);
    wf = min(max(wf, 0), HP_MAX);
    wc = min(max(wc, 0), HP_MAX);

    float dH = (float)hc - Hu;
    float dW = (float)wc - Wu;
    float eH = 1.0f - dH;
    float eW = 1.0f - dW;

    // local (smem) coords
    int lhf = hf - ph0, lhc = hc - ph0;
    int lwf = wf - pw0, lwc = wc - pw0;

    float v00, v10, v01, v11;
    // all four in-tile?  (lhf<=lhc, lwf<=lwc due to monotone clamp, so 3 tests suffice)
    if (((lhf | lwf) >= 0) & (lhc <= SDIM - 1) & (lwc <= SDIM - 1)) {
        v00 = s[lhf * SSTR + lwf];
        v01 = s[lhf * SSTR + lwc];
        v10 = s[lhc * SSTR + lwf];
        v11 = s[lhc * SSTR + lwc];
    } else {
        // astronomically rare for N(0,1) flow; exact-correct fallback
        v00 = fetch_padded(img, hf, wf);
        v01 = fetch_padded(img, hf, wc);
        v10 = fetch_padded(img, hc, wf);
        v11 = fetch_padded(img, hc, wc);
    }

    return v00 * (dW * dH) + v10 * (dW * eH) + v01 * (eW * dH) + v11 * (eW * eH);
}

__global__ void __launch_bounds__(256)
dense_warp_smem_kernel(const float* __restrict__ img,
                       const float* __restrict__ flowH,
                       const float* __restrict__ flowW,
                       float* __restrict__ out) {
    __shared__ float s[SDIM * SSTR];

    const int tid = threadIdx.x;
    const int h0 = blockIdx.y * TILE;
    const int w0 = blockIdx.x * TILE;
    const int ph0 = h0 + 1 - HALO;   // padded coord of smem row 0
    const int pw0 = w0 + 1 - HALO;

    // ---- stage 82x82 padded window (zero outside image) ----
    #pragma unroll 1
    for (int i = tid; i < SDIM * SDIM; i += 256) {
        int r = i / SDIM;
        int c = i - r * SDIM;
        int p = ph0 + r;            // padded row
        int q = pw0 + c;            // padded col
        float v = 0.0f;
        if ((p >= 1) & (p <= H_DIM) & (q >= 1) & (q <= W_DIM))
            v = __ldg(img + (size_t)(p - 1) * W_DIM + (q - 1));
        s[r * SSTR + c] = v;
    }
    __syncthreads();

    // ---- compute: each thread does 4 rows x 4 consecutive pixels ----
    const int tx = tid & 15;         // 0..15  -> w = w0 + 4*tx
    const int ty = tid >> 4;         // 0..15  -> rows ty + 16*k
    const int w = w0 + tx * 4;

    #pragma unroll
    for (int k = 0; k < 4; k++) {
        const int h = h0 + ty + 16 * k;
        const size_t base = (size_t)h * W_DIM + w;

        float4 fh = *reinterpret_cast<const float4*>(flowH + base);
        float4 fw = *reinterpret_cast<const float4*>(flowW + base);

        float4 o;
        o.x = warp_one(s, img, fh.x, fw.x, h, w + 0, ph0, pw0);
        o.y = warp_one(s, img, fh.y, fw.y, h, w + 1, ph0, pw0);
        o.z = warp_one(s, img, fh.z, fw.z, h, w + 2, ph0, pw0);
        o.w = warp_one(s, img, fh.w, fw.w, h, w + 3, ph0, pw0);

        *reinterpret_cast<float4*>(out + base) = o;
    }
}

extern "C" void kernel_launch(void* const* d_in, const int* in_sizes, int n_in,
                              void* d_out, int out_size) {
    const float* img   = (const float*)d_in[0];
    const float* flowH = (const float*)d_in[1];
    const float* flowW = (const float*)d_in[1] + (size_t)H_DIM * W_DIM;
    float* out = (float*)d_out;

    dim3 grid(W_DIM / TILE, H_DIM / TILE);   // 64 x 64
    dense_warp_smem_kernel<<<grid, 256>>>(img, flowH, flowW, out);
}

// round 4
// speedup vs baseline: 1.0713x; 1.0713x over previous
#include <cuda_runtime.h>
#include <cstdint>

// Dense 2D spatial transformer (bilinear warp, zero-padded border).
// Direct-gather version with a 2D-compact warp footprint (32 cols x 4 rows per
// warp) to minimize L1tex wavefronts per gather instruction.
//
// input1: [1,1,4096,4096] f32 image
// input2: [1,2,4096,4096] f32 flow (plane 0 = dH, plane 1 = dW)
// out:    [1,1,4096,4096] f32
//
// Reference semantics (padded coords in [0,4097], zero border):
//   H_up = flow_h + h + 1 ; W_up = flow_w + w + 1
//   hf = clip(floor(H_up),0,4097); hc = clip(hf+1,0,4097); same for w
//   dH = hc - H_up; dW = wc - W_up   (weights from CLIPPED coords)
//   out = v(hf,wf)*dW*dH + v(hc,wf)*dW*(1-dH) + v(hf,wc)*(1-dW)*dH + v(hc,wc)*(1-dW)*(1-dH)

#define H_DIM 4096
#define W_DIM 4096
#define HP_MAX 4097

__device__ __forceinline__ float fetch_padded(const float* __restrict__ img, int h, int w) {
    // padded (h,w) -> img[(h-1)<<12 | (w-1)] when interior, else 0
    bool in = ((unsigned)(h - 1) < (unsigned)H_DIM) & ((unsigned)(w - 1) < (unsigned)W_DIM);
    int idx = ((h - 1) << 12) + (w - 1);
    return in ? __ldg(img + idx) : 0.0f;
}

__device__ __forceinline__ float warp_one(const float* __restrict__ img,
                                          float flow_h, float flow_w,
                                          float hp1, float wp1) {
    float Hu = flow_h + hp1;   // h + 1 as float, precomputed
    float Wu = flow_w + wp1;

    int hf = __float2int_rd(Hu);
    int wf = __float2int_rd(Wu);
    int hc = hf + 1;
    int wc = wf + 1;

    hf = min(max(hf, 0), HP_MAX);
    hc = min(max(hc, 0), HP_MAX);
    wf = min(max(wf, 0), HP_MAX);
    wc = min(max(wc, 0), HP_MAX);

    float dH = (float)hc - Hu;
    float dW = (float)wc - Wu;
    float eH = 1.0f - dH;
    float eW = 1.0f - dW;

    float v00 = fetch_padded(img, hf, wf);
    float v10 = fetch_padded(img, hc, wf);
    float v01 = fetch_padded(img, hf, wc);
    float v11 = fetch_padded(img, hc, wc);

    return v00 * (dW * dH) + v10 * (dW * eH) + v01 * (eW * dH) + v11 * (eW * eH);
}

// Block tile: 64 (w) x 16 (h). Warp tile: 32 (w) x 4 (h).
// Lane layout within warp: lx = lane&7 (column quad), ly = lane>>3 (row).
__global__ void __launch_bounds__(256)
dense_warp_kernel(const float* __restrict__ img,
                  const float* __restrict__ flowH,
                  const float* __restrict__ flowW,
                  float* __restrict__ out) {
    const int tid  = threadIdx.x;
    const int warp = tid >> 5;
    const int lane = tid & 31;
    const int lx   = lane & 7;
    const int ly   = lane >> 3;

    // 2 warps across w, 4 warps down h
    const int w = (blockIdx.x << 6) + ((warp & 1) << 5) + (lx << 2);
    const int h = (blockIdx.y << 4) + ((warp >> 1) << 2) + ly;

    const int base = (h << 12) + w;   // fits in 31 bits (16M elements)

    float4 fh = *reinterpret_cast<const float4*>(flowH + base);
    float4 fw = *reinterpret_cast<const float4*>(flowW + base);

    const float hp1 = (float)(h + 1);
    const float wp1 = (float)(w + 1);

    float4 o;
    o.x = warp_one(img, fh.x, fw.x, hp1, wp1 + 0.0f);
    o.y = warp_one(img, fh.y, fw.y, hp1, wp1 + 1.0f);
    o.z = warp_one(img, fh.z, fw.z, hp1, wp1 + 2.0f);
    o.w = warp_one(img, fh.w, fw.w, hp1, wp1 + 3.0f);

    *reinterpret_cast<float4*>(out + base) = o;
}

extern "C" void kernel_launch(void* const* d_in, const int* in_sizes, int n_in,
                              void* d_out, int out_size) {
    const float* img   = (const float*)d_in[0];
    const float* flowH = (const float*)d_in[1];
    const float* flowW = (const float*)d_in[1] + (size_t)H_DIM * W_DIM;
    float* out = (float*)d_out;

    dim3 grid(W_DIM / 64, H_DIM / 16);   // 64 x 256 = 16384 blocks
    dense_warp_kernel<<<grid, 256>>>(img, flowH, flowW, out);
}

// round 5
// speedup vs baseline: 1.3044x; 1.2176x over previous
#include <cuda_runtime.h>
#include <cstdint>

// Dense 2D spatial transformer (bilinear warp, zero-padded border).
// Direct-gather with interior fast path: for pixels whose 2x2 tap square is
// fully interior (all but ~0.8% near the border), skip all clamping and use a
// single base index + immediate-offset loads.
//
// input1: [1,1,4096,4096] f32 image
// input2: [1,2,4096,4096] f32 flow (plane 0 = dH, plane 1 = dW)
// out:    [1,1,4096,4096] f32
//
// Reference semantics (padded coords in [0,4097], zero border):
//   H_up = flow_h + h + 1 ; W_up = flow_w + w + 1
//   hf = clip(floor(H_up),0,4097); hc = clip(hf+1,0,4097); same for w
//   dH = hc - H_up; dW = wc - W_up   (weights from CLIPPED coords)
//   out = v(hf,wf)*dW*dH + v(hc,wf)*dW*(1-dH) + v(hf,wc)*(1-dW)*dH + v(hc,wc)*(1-dW)*(1-dH)

#define H_DIM 4096
#define W_DIM 4096
#define HP_MAX 4097

__device__ __forceinline__ float fetch_padded(const float* __restrict__ img, int h, int w) {
    bool in = ((unsigned)(h - 1) < (unsigned)H_DIM) & ((unsigned)(w - 1) < (unsigned)W_DIM);
    int idx = ((h - 1) << 12) + (w - 1);
    return in ? __ldg(img + idx) : 0.0f;
}

__device__ __forceinline__ float warp_one(const float* __restrict__ img,
                                          float flow_h, float flow_w,
                                          float hp1, float wp1) {
    float Hu = flow_h + hp1;
    float Wu = flow_w + wp1;

    float fhf = floorf(Hu);
    float fwf = floorf(Wu);
    int hf = (int)fhf;
    int wf = (int)fwf;

    float v00, v01, v10, v11, dH, dW;

    // fast path: hf in [1,4095] and wf in [1,4095] -> all 4 taps interior, no clamps
    if (((unsigned)(hf - 1) <= 4094u) & ((unsigned)(wf - 1) <= 4094u)) {
        dH = (fhf + 1.0f) - Hu;
        dW = (fwf + 1.0f) - Wu;
        int idx = (hf << 12) + wf - (W_DIM + 1);   // (hf-1)*4096 + (wf-1)
        v00 = __ldg(img + idx);
        v01 = __ldg(img + idx + 1);
        v10 = __ldg(img + idx + W_DIM);
        v11 = __ldg(img + idx + W_DIM + 1);
    } else {
        int hc = hf + 1, wc = wf + 1;
        int hfc = min(max(hf, 0), HP_MAX);
        int hcc = min(max(hc, 0), HP_MAX);
        int wfc = min(max(wf, 0), HP_MAX);
        int wcc = min(max(wc, 0), HP_MAX);
        dH = (float)hcc - Hu;
        dW = (float)wcc - Wu;
        v00 = fetch_padded(img, hfc, wfc);
        v01 = fetch_padded(img, hfc, wcc);
        v10 = fetch_padded(img, hcc, wfc);
        v11 = fetch_padded(img, hcc, wcc);
    }

    float eH = 1.0f - dH;
    float eW = 1.0f - dW;
    // dH*(dW*v00 + eW*v01) + eH*(dW*v10 + eW*v11)
    float a = fmaf(eW, v01, dW * v00);
    float b = fmaf(eW, v11, dW * v10);
    return fmaf(eH, b, dH * a);
}

__global__ void __launch_bounds__(256)
dense_warp_kernel(const float* __restrict__ img,
                  const float* __restrict__ flowH,
                  const float* __restrict__ flowW,
                  float* __restrict__ out) {
    int t = blockIdx.x * blockDim.x + threadIdx.x;
    int base = t << 2;                       // 4 consecutive pixels, same row

    float4 fh = *reinterpret_cast<const float4*>(flowH + base);
    float4 fw = *reinterpret_cast<const float4*>(flowW + base);

    int h = base >> 12;
    int w = base & (W_DIM - 1);

    const float hp1 = (float)(h + 1);
    const float wp1 = (float)(w + 1);

    float4 o;
    o.x = warp_one(img, fh.x, fw.x, hp1, wp1 + 0.0f);
    o.y = warp_one(img, fh.y, fw.y, hp1, wp1 + 1.0f);
    o.z = warp_one(img, fh.z, fw.z, hp1, wp1 + 2.0f);
    o.w = warp_one(img, fh.w, fw.w, hp1, wp1 + 3.0f);

    *reinterpret_cast<float4*>(out + base) = o;
}

extern "C" void kernel_launch(void* const* d_in, const int* in_sizes, int n_in,
                              void* d_out, int out_size) {
    const float* img   = (const float*)d_in[0];
    const float* flowH = (const float*)d_in[1];
    const float* flowW = (const float*)d_in[1] + (size_t)H_DIM * W_DIM;
    float* out = (float*)d_out;

    const int n_pix = H_DIM * W_DIM;
    const int threads = 256;
    const int blocks = (n_pix / 4) / threads;   // 16384
    dense_warp_kernel<<<blocks, threads>>>(img, flowH, flowW, out);
}

// round 6
// speedup vs baseline: 1.3653x; 1.0467x over previous
#include <cuda_runtime.h>
#include <cstdint>

// Dense 2D spatial transformer (bilinear warp, zero-padded border).
// R5: two-phase structure — batch all 16 gathers per thread (MLP=16) before
// any combine math; __launch_bounds__(256,4) to give ptxas register room.
//
// input1: [1,1,4096,4096] f32 image
// input2: [1,2,4096,4096] f32 flow (plane 0 = dH, plane 1 = dW)
// out:    [1,1,4096,4096] f32
//
// Reference semantics (padded coords in [0,4097], zero border):
//   H_up = flow_h + h + 1 ; W_up = flow_w + w + 1
//   hf = clip(floor(H_up),0,4097); hc = clip(hf+1,0,4097); same for w
//   dH = hc - H_up; dW = wc - W_up   (weights from CLIPPED coords)
//   out = v00*dW*dH + v10*dW*(1-dH) + v01*(1-dW)*dH + v11*(1-dW)*(1-dH)

#define H_DIM 4096
#define W_DIM 4096
#define HP_MAX 4097

__device__ __forceinline__ float fetch_padded(const float* __restrict__ img, int h, int w) {
    bool in = ((unsigned)(h - 1) < (unsigned)H_DIM) & ((unsigned)(w - 1) < (unsigned)W_DIM);
    int idx = ((h - 1) << 12) + (w - 1);
    return in ? __ldg(img + idx) : 0.0f;
}

__global__ void __launch_bounds__(256, 4)
dense_warp_kernel(const float* __restrict__ img,
                  const float* __restrict__ flowH,
                  const float* __restrict__ flowW,
                  float* __restrict__ out) {
    int t = blockIdx.x * blockDim.x + threadIdx.x;
    int base = t << 2;                       // 4 consecutive pixels, same row

    float4 fh = *reinterpret_cast<const float4*>(flowH + base);
    float4 fw = *reinterpret_cast<const float4*>(flowW + base);

    int h = base >> 12;
    int w = base & (W_DIM - 1);

    const float hp1 = (float)(h + 1);
    const float wp1 = (float)(w + 1);

    float fhv[4] = {fh.x, fh.y, fh.z, fh.w};
    float fwv[4] = {fw.x, fw.y, fw.z, fw.w};

    float v00[4], v01[4], v10[4], v11[4];
    float dH[4], dW[4];

    // ---- phase 1: indices + issue all 16 gathers ----
    #pragma unroll
    for (int k = 0; k < 4; k++) {
        float Hu = fhv[k] + hp1;
        float Wu = fwv[k] + wp1 + (float)k;

        float fhf = floorf(Hu);
        float fwf = floorf(Wu);
        int hf = (int)fhf;
        int wf = (int)fwf;

        if (((unsigned)(hf - 1) <= 4094u) & ((unsigned)(wf - 1) <= 4094u)) {
            // interior fast path: one base index, immediate offsets
            dH[k] = (fhf + 1.0f) - Hu;
            dW[k] = (fwf + 1.0f) - Wu;
            int idx = (hf << 12) + wf - (W_DIM + 1);   // (hf-1)*4096 + (wf-1)
            v00[k] = __ldg(img + idx);
            v01[k] = __ldg(img + idx + 1);
            v10[k] = __ldg(img + idx + W_DIM);
            v11[k] = __ldg(img + idx + W_DIM + 1);
        } else {
            int hc = hf + 1, wc = wf + 1;
            int hfc = min(max(hf, 0), HP_MAX);
            int hcc = min(max(hc, 0), HP_MAX);
            int wfc = min(max(wf, 0), HP_MAX);
            int wcc = min(max(wc, 0), HP_MAX);
            dH[k] = (float)hcc - Hu;
            dW[k] = (float)wcc - Wu;
            v00[k] = fetch_padded(img, hfc, wfc);
            v01[k] = fetch_padded(img, hfc, wcc);
            v10[k] = fetch_padded(img, hcc, wfc);
            v11[k] = fetch_padded(img, hcc, wcc);
        }
    }

    // ---- phase 2: pure-FMA combine ----
    float o[4];
    #pragma unroll
    for (int k = 0; k < 4; k++) {
        float eH = 1.0f - dH[k];
        float eW = 1.0f - dW[k];
        float a = fmaf(eW, v01[k], dW[k] * v00[k]);
        float b = fmaf(eW, v11[k], dW[k] * v10[k]);
        o[k] = fmaf(eH, b, dH[k] * a);
    }

    float4 ov = make_float4(o[0], o[1], o[2], o[3]);
    *reinterpret_cast<float4*>(out + base) = ov;
}

extern "C" void kernel_launch(void* const* d_in, const int* in_sizes, int n_in,
                              void* d_out, int out_size) {
    const float* img   = (const float*)d_in[0];
    const float* flowH = (const float*)d_in[1];
    const float* flowW = (const float*)d_in[1] + (size_t)H_DIM * W_DIM;
    float* out = (float*)d_out;

    const int n_pix = H_DIM * W_DIM;
    const int threads = 256;
    const int blocks = (n_pix / 4) / threads;   // 16384
    dense_warp_kernel<<<blocks, threads>>>(img, flowH, flowW, out);
}